// round 16
// baseline (speedup 1.0000x reference)
#include <cuda_runtime.h>
#include <cuda_fp16.h>
#include <cstdint>

// out[b,n,f] = sum_m A[b,n,m] * X[b,m,f] + bias[f]
// A: [8,4096,4096] fp32, X: [8,4096,64] fp32, bias [64].
//
// Warp-desynchronized single-launch kernel (R15 with the swizzle bug fixed:
// SW() is now applied to the FULL byte offset of every staged row, since the
// per-iteration strides (256B / 512B) land inside the swizzle's bit-7..9
// source field).
//  - Consumer warps (wid<NG) each own 16 M-rows AND a private 2x2KB A
//    double-buffer: LDG fp32 -> cvt fp16 -> STS -> ldmatrix, warp-local only.
//  - Warp 7 is a dedicated B producer: cp.async from fp16 g_Xt into a
//    4-stage mbarrier ring (full: count 1; empty: count NG).
//  - Convert phase (X -> g_Xt) + global software barrier as in R13.
// Grid 296 = 2 CTAs/SM exact; 16-row balanced split (6/7 groups per CTA).

#define NBATCH  8
#define NN      4096
#define FF      64
#define CTAS_B  37
#define GRID    (NBATCH * CTAS_B)   // 296
#define NSUB    64                  // KC=64 sub-chunks
#define BSTAGES 4

#define A_WBUF  2048                // 16 rows x 128B fp16 (one sub-chunk, one warp)
#define OFF_BQ  (7 * 2 * A_WBUF)    // 28672: after 7 warps x double buffer
#define B_ST    8192                // 64 f-rows x 128B fp16
#define SMEM_DYN (OFF_BQ + BSTAGES * B_ST + 256)   // 61696

__device__ __half g_Xt[NBATCH * FF * NN];   // [b][f][k] fp16
__device__ unsigned g_bar = 0;              // monotonic epoch barrier counter

__device__ __forceinline__ uint32_t smem_u32(const void* p) {
    uint32_t a;
    asm("{ .reg .u64 t; cvta.to.shared.u64 t, %1; cvt.u32.u64 %0, t; }"
        : "=r"(a) : "l"(p));
    return a;
}
#define SW(o) ((o) ^ (((o) >> 3) & 0x70))

#define MBAR_INIT(addr, cnt) \
    asm volatile("mbarrier.init.shared.b64 [%0], %1;" :: "r"(addr), "r"(cnt) : "memory")
#define MBAR_ARRIVE(addr) \
    asm volatile("mbarrier.arrive.release.cta.shared::cta.b64 _, [%0];" \
                 :: "r"(addr) : "memory")
#define MBAR_WAIT(addr, parity) do {                                        \
    uint32_t _m = (addr), _p = (parity), _d;                                \
    asm volatile("{\n\t.reg .pred p;\n\t"                                   \
        "mbarrier.try_wait.parity.acquire.cta.shared::cta.b64 p, [%1], %2;\n\t" \
        "selp.b32 %0, 1, 0, p;\n\t}" : "=r"(_d) : "r"(_m), "r"(_p) : "memory"); \
    if (!_d) {                                                              \
        asm volatile("{\n\t.reg .pred P1;\n\t"                              \
            "W%=:\n\t"                                                      \
            "mbarrier.try_wait.parity.acquire.cta.shared::cta.b64 P1, [%0], %1, 0x989680;\n\t" \
            "@P1 bra.uni D%=;\n\t"                                          \
            "bra.uni W%=;\n\t"                                              \
            "D%=:\n\t}" :: "r"(_m), "r"(_p) : "memory");                    \
    }                                                                       \
} while (0)

#define CPB16(dst, src) \
    asm volatile("cp.async.cg.shared.global [%0], [%1], 16;" \
                 :: "r"(dst), "l"(src) : "memory")
#define CP_COMMIT() asm volatile("cp.async.commit_group;" ::: "memory")
#define CP_WAIT0()  asm volatile("cp.async.wait_group 0;" ::: "memory")

__global__ __launch_bounds__(256, 2) void gemm_f16_desync2(
    const float* __restrict__ A,
    const float* __restrict__ X,
    const float* __restrict__ bias,
    float* __restrict__ out)
{
    extern __shared__ char ds[];
    __shared__ __align__(8) uint64_t mb[2 * BSTAGES];   // full[0..3], empty[0..3]
    const uint32_t sb = smem_u32(ds);
    const uint32_t mbb = smem_u32(mb);
#define FULLB(s)  (mbb + (uint32_t)(s) * 8u)
#define EMPTYB(s) (mbb + (uint32_t)(BSTAGES + (s)) * 8u)

    const int tid  = threadIdx.x;
    const int wid  = tid >> 5;
    const int lane = tid & 31;

    const int b  = blockIdx.x / CTAS_B;
    const int ct = blockIdx.x % CTAS_B;
    const int g0 = (ct * 256) / CTAS_B;
    const int g1 = ((ct + 1) * 256) / CTAS_B;
    const int NG = g1 - g0;             // 6 or 7 (16-row groups)

    if (tid == 0) {
#pragma unroll
        for (int s = 0; s < BSTAGES; ++s) {
            MBAR_INIT(FULLB(s), 1);
            MBAR_INIT(EMPTYB(s), (uint32_t)NG);
        }
    }
    __syncthreads();

    // ================= phase 1: convert X -> g_Xt (my slab share) ==========
    {
        float* tt = reinterpret_cast<float*>(ds);     // [32][65]
        const int tx = tid & 31;
        const int ty = tid >> 5;
        const int s0 = (blockIdx.x * 1024) / GRID;
        const int s1 = ((blockIdx.x + 1) * 1024) / GRID;
        for (int s = s0; s < s1; ++s) {
            const int cb = s >> 7;
            const int k0 = (s & 127) * 32;
#pragma unroll
            for (int i = 0; i < 4; ++i) {
                const int r = ty + 8 * i;
                const float* src = X + ((size_t)cb * NN + k0 + r) * FF;
                tt[r * 65 + tx]      = src[tx];
                tt[r * 65 + tx + 32] = src[tx + 32];
            }
            __syncthreads();
#pragma unroll
            for (int j = 0; j < 8; ++j) {
                const int f = ty + 8 * j;
                g_Xt[((size_t)cb * FF + f) * NN + k0 + tx] =
                    __float2half_rn(tt[tx * 65 + f]);
            }
            __syncthreads();
        }
    }

    // ---- arrive at global barrier (release) ----
    __threadfence();
    __syncthreads();
    unsigned bar_target = 0;
    if (tid == 0) {
        const unsigned my = atomicAdd(&g_bar, 1u);
        bar_target = my - (my % (unsigned)GRID) + (unsigned)GRID;
    }

    // ================= consumer/producer setup ==============================
    const float*  Ab = A + ((size_t)b * NN + (size_t)g0 * 16) * NN;
    const __half* XtB = g_Xt + (size_t)b * FF * NN;

    // consumer A addressing: my rows = (g0+wid)*16 .. +15
    const int a_lrow = lane >> 4;            // 0/1
    const int a_c4   = lane & 15;
    const float* a_ld =
        Ab + ((size_t)(wid * 16 + a_lrow)) * NN + a_c4 * 4;   // + 2i*NN + s*64
    const uint32_t myA = sb + (uint32_t)wid * (2 * A_WBUF);

    // consumer ldmatrix (local rows 0..15 of my 2KB buffer)
    const int li = lane >> 3;
    const int lr = lane & 7;
    const uint32_t a_off =
        (uint32_t)(((li & 1) * 8 + lr) * 128 + (li >> 1) * 16);
    const uint32_t b_off =
        (uint32_t)(((li >> 1) * 8 + lr) * 128 + (li & 1) * 16);
    const uint32_t Bq = sb + OFF_BQ;

    // producer B addressing: row = 4i + p_row0, col seg p_c16
    const int p_row0 = lane >> 3;            // 0..3
    const int p_c16  = lane & 7;
    const __half* p_src = XtB + (size_t)p_row0 * NN + p_c16 * 8;  // +4i*NN + s*64

    float acc[8][4];
#pragma unroll
    for (int n = 0; n < 8; ++n)
#pragma unroll
        for (int j = 0; j < 4; ++j) acc[n][j] = 0.0f;

    float4 pa[8];

    auto ldg_a = [&](int s) {
        const size_t ko = (size_t)s * 64;
#pragma unroll
        for (int i = 0; i < 8; ++i)
            pa[i] = *reinterpret_cast<const float4*>(
                a_ld + (size_t)(2 * i) * NN + ko);
    };
    auto sts_a = [&](uint32_t abase) {
#pragma unroll
        for (int i = 0; i < 8; ++i) {
            __half2 h0 = __floats2half2_rn(pa[i].x, pa[i].y);
            __half2 h1 = __floats2half2_rn(pa[i].z, pa[i].w);
            // FIX: swizzle the FULL offset (i*256 toggles swizzle source bits)
            const uint32_t o =
                (uint32_t)((2 * i + a_lrow) * 128 + a_c4 * 8);
            asm volatile("st.shared.v2.b32 [%0], {%1, %2};"
                         :: "r"(abase + SW(o)),
                            "r"(*(uint32_t*)&h0), "r"(*(uint32_t*)&h1)
                         : "memory");
        }
    };
    auto compute_sub = [&](uint32_t abase, uint32_t bbase) {
#pragma unroll
        for (int ks = 0; ks < 4; ++ks) {
            uint32_t a0, a1, a2, a3;
            asm volatile(
                "ldmatrix.sync.aligned.m8n8.x4.shared.b16 {%0,%1,%2,%3}, [%4];"
                : "=r"(a0), "=r"(a1), "=r"(a2), "=r"(a3)
                : "r"(abase + SW(a_off + (uint32_t)ks * 32)));
#pragma unroll
            for (int p = 0; p < 4; ++p) {
                uint32_t b0, b1, b2, b3;
                asm volatile(
                    "ldmatrix.sync.aligned.m8n8.x4.shared.b16 {%0,%1,%2,%3}, [%4];"
                    : "=r"(b0), "=r"(b1), "=r"(b2), "=r"(b3)
                    : "r"(bbase + SW(b_off + (uint32_t)p * 2048 + (uint32_t)ks * 32)));
                asm volatile(
                    "mma.sync.aligned.m16n8k16.row.col.f32.f16.f16.f32 "
                    "{%0,%1,%2,%3}, {%4,%5,%6,%7}, {%8,%9}, {%0,%1,%2,%3};"
                    : "+f"(acc[2*p][0]), "+f"(acc[2*p][1]),
                      "+f"(acc[2*p][2]), "+f"(acc[2*p][3])
                    : "r"(a0), "r"(a1), "r"(a2), "r"(a3), "r"(b0), "r"(b1));
                asm volatile(
                    "mma.sync.aligned.m16n8k16.row.col.f32.f16.f16.f32 "
                    "{%0,%1,%2,%3}, {%4,%5,%6,%7}, {%8,%9}, {%0,%1,%2,%3};"
                    : "+f"(acc[2*p+1][0]), "+f"(acc[2*p+1][1]),
                      "+f"(acc[2*p+1][2]), "+f"(acc[2*p+1][3])
                    : "r"(a0), "r"(a1), "r"(a2), "r"(a3), "r"(b2), "r"(b3));
            }
        }
    };

    // ---- pre-barrier A staging (A never needs g_Xt) ----
    if (wid < NG) ldg_a(0);

    // ---- wait at global barrier (acquire) ----
    if (tid == 0) {
        unsigned v;
        do {
            asm volatile("ld.acquire.gpu.global.u32 %0, [%1];"
                         : "=r"(v) : "l"(&g_bar));
            if (v >= bar_target) break;
            __nanosleep(32);
        } while (true);
    }
    __syncthreads();

    // ================= main phase: desynchronized warps =====================
    if (wid == 7) {
        // ---- B producer: 4-stage cp.async ring ----
        for (int s = 0; s < NSUB; ++s) {
            const int st = s & (BSTAGES - 1);
            if (s >= BSTAGES)
                MBAR_WAIT(EMPTYB(st), (uint32_t)((((s >> 2) - 1) & 1)));
            const uint32_t bdst = Bq + (uint32_t)st * B_ST;
            const __half* src = p_src + (size_t)s * 64;
#pragma unroll
            for (int i = 0; i < 16; ++i) {
                // FIX: swizzle the FULL offset (i*512 toggles swizzle bits)
                const uint32_t o =
                    (uint32_t)((4 * i + p_row0) * 128 + p_c16 * 16);
                CPB16(bdst + SW(o), src + (size_t)(4 * i) * NN);
            }
            CP_COMMIT();
            CP_WAIT0();
            __syncwarp();
            if (lane == 0) MBAR_ARRIVE(FULLB(st));
        }
    } else if (wid < NG) {
        // ---- consumer: self-paced, warp-private A double buffer ----
        sts_a(myA);          // sub 0 (regs loaded pre-barrier)
        ldg_a(1);
        __syncwarp();
        for (int s = 0; s < NSUB; ++s) {
            const int st = s & (BSTAGES - 1);
            const uint32_t abuf = myA + (uint32_t)(s & 1) * A_WBUF;

            MBAR_WAIT(FULLB(st), (uint32_t)((s >> 2) & 1));
            compute_sub(abuf, Bq + (uint32_t)st * B_ST);
            if (lane == 0) MBAR_ARRIVE(EMPTYB(st));

            if (s + 1 < NSUB) sts_a(myA + (uint32_t)((s + 1) & 1) * A_WBUF);
            if (s + 2 < NSUB) ldg_a(s + 2);
            __syncwarp();
        }
    }

    // ---- epilogue: add bias, store ----
    if (wid < NG) {
        const int g = lane >> 2, q = lane & 3;
        const int mlo = (g0 + wid) * 16 + g;
        float* o0 = out + ((size_t)b * NN + mlo) * FF;
        float* o1 = o0 + (size_t)8 * FF;
#pragma unroll
        for (int nt = 0; nt < 8; ++nt) {
            const int col = nt * 8 + q * 2;
            const float2 bv = *reinterpret_cast<const float2*>(bias + col);
            float2 v0 = make_float2(acc[nt][0] + bv.x, acc[nt][1] + bv.y);
            float2 v1 = make_float2(acc[nt][2] + bv.x, acc[nt][3] + bv.y);
            *reinterpret_cast<float2*>(o0 + col) = v0;
            *reinterpret_cast<float2*>(o1 + col) = v1;
        }
    }
}

extern "C" void kernel_launch(void* const* d_in, const int* in_sizes, int n_in,
                              void* d_out, int out_size)
{
    const float* A    = (const float*)d_in[0]; // adjacent [8,4096,4096]
    const float* X    = (const float*)d_in[1]; // annotations [8,4096,64]
    const float* bias = (const float*)d_in[2]; // bias [1,1,64]
    float* out = (float*)d_out;

    cudaFuncSetAttribute(gemm_f16_desync2,
                         cudaFuncAttributeMaxDynamicSharedMemorySize, SMEM_DYN);

    gemm_f16_desync2<<<GRID, 256, SMEM_DYN>>>(A, X, bias, out);
}

// round 17
// speedup vs baseline: 1.0369x; 1.0369x over previous
#include <cuda_runtime.h>
#include <cuda_fp16.h>
#include <cstdint>

// out[b,n,f] = sum_m A[b,n,m] * X[b,m,f] + bias[f]
// A: [8,4096,4096] fp32, X: [8,4096,64] fp32, bias [64].
//
// FINAL (R13, the measured optimum at 99.1us total / 95.9us kernel):
//  - Single launch. Phase 1 converts X -> g_Xt ([b][f][k] fp16) split over
//    all CTAs; global epoch-counter software barrier (grid = 296 = exactly
//    2 CTAs/SM, one resident wave, so all CTAs co-run; counter is monotonic
//    so CUDA-graph replays stay correct).
//  - Pre-barrier A staging: A never depends on g_Xt, so A sub0 is LDG+STS'd
//    and A sub1 prefetched into registers before the spin; post-barrier
//    prologue is B-only.
//  - GEMM core (R9): fp16 mma.sync.m16n8k16 with fp32 accum, register-staged
//    double buffer, two KC=64 sub-chunks per iteration (one __syncthreads
//    per 128 k), SW128-swizzled smem, 16-row balanced split over 37 CTAs
//    per batch (6 or 7 groups per CTA; all 8 warps load, NG warps compute).
//  Measured: DRAM 73% (5.8 TB/s — the practical ceiling for this access mix,
//  established by 11 structural experiments), rel_err 2.519e-4.

#define NBATCH  8
#define NN      4096
#define FF      64
#define CTAS_B  37
#define GRID    (NBATCH * CTAS_B)   // 296
#define MAXG    7
#define NSUB    64                  // KC=64 sub-chunks
#define NIT     32                  // 2 sub-chunks per iteration

#define SUB_A   14336               // 112 rows x 128B fp16
#define SUB_B   8192                // 64 f-rows x 128B fp16
#define STB2    (2 * (SUB_A + SUB_B))   // 45056 per stage
#define OFF_B   (2 * SUB_A)             // 28672 within stage
#define SMEM_DYN (2 * STB2)             // 90112

__device__ __half g_Xt[NBATCH * FF * NN];   // [b][f][k] fp16
__device__ unsigned g_bar = 0;              // monotonic epoch barrier counter

__device__ __forceinline__ uint32_t smem_u32(const void* p) {
    uint32_t a;
    asm("{ .reg .u64 t; cvta.to.shared.u64 t, %1; cvt.u32.u64 %0, t; }"
        : "=r"(a) : "l"(p));
    return a;
}
#define SW(o) ((o) ^ (((o) >> 3) & 0x70))

__global__ __launch_bounds__(256, 2) void gemm_f16_final(
    const float* __restrict__ A,
    const float* __restrict__ X,
    const float* __restrict__ bias,
    float* __restrict__ out)
{
    extern __shared__ char ds[];
    const uint32_t sb = smem_u32(ds);

    const int tid  = threadIdx.x;
    const int wid  = tid >> 5;
    const int lane = tid & 31;

    // ================= phase 1: convert X -> g_Xt (my slab share) ==========
    {
        float* tt = reinterpret_cast<float*>(ds);     // [32][65]
        const int tx = tid & 31;
        const int ty = tid >> 5;
        const int s0 = (blockIdx.x * 1024) / GRID;
        const int s1 = ((blockIdx.x + 1) * 1024) / GRID;
        for (int s = s0; s < s1; ++s) {
            const int cb = s >> 7;
            const int k0 = (s & 127) * 32;
#pragma unroll
            for (int i = 0; i < 4; ++i) {
                const int r = ty + 8 * i;
                const float* src = X + ((size_t)cb * NN + k0 + r) * FF;
                tt[r * 65 + tx]      = src[tx];
                tt[r * 65 + tx + 32] = src[tx + 32];
            }
            __syncthreads();
#pragma unroll
            for (int j = 0; j < 8; ++j) {
                const int f = ty + 8 * j;
                g_Xt[((size_t)cb * FF + f) * NN + k0 + tx] =
                    __float2half_rn(tt[tx * 65 + f]);
            }
            __syncthreads();
        }
    }

    // ---- arrive at global barrier (release) ----
    __threadfence();
    __syncthreads();
    unsigned bar_target = 0;
    if (tid == 0) {
        const unsigned my = atomicAdd(&g_bar, 1u);
        bar_target = my - (my % (unsigned)GRID) + (unsigned)GRID;
    }

    // ================= phase 2: GEMM (R9 core) =============================
    const int b  = blockIdx.x / CTAS_B;
    const int ct = blockIdx.x % CTAS_B;
    const int g0 = (ct * 256) / CTAS_B;
    const int g1 = ((ct + 1) * 256) / CTAS_B;
    const int NG = g1 - g0;             // 6 or 7 (16-row groups)
    const int nrows = NG * 16;

    const float*  Ab = A + ((size_t)b * NN + (size_t)g0 * 16) * NN;
    const __half* Xb = g_Xt + (size_t)b * FF * NN;

    const int arow = tid >> 4;
    const int ac4  = tid & 15;
    const int brow = tid >> 3;
    const int bc   = tid & 7;
    const float*  a_ld = Ab + (size_t)arow * NN + ac4 * 4;
    const __half* b_ld = Xb + (size_t)brow * NN + bc * 8;
    const uint32_t a_sts = SW((uint32_t)(arow * 128 + ac4 * 8));
    const uint32_t b_sts = SW((uint32_t)(brow * 128 + bc * 16));

    const int li = lane >> 3;
    const int lr = lane & 7;
    const uint32_t a_off =
        (uint32_t)((wid * 16 + (li & 1) * 8 + lr) * 128 + (li >> 1) * 16);
    const uint32_t b_off =
        (uint32_t)(((li >> 1) * 8 + lr) * 128 + (li & 1) * 16);

    float acc[8][4];
#pragma unroll
    for (int n = 0; n < 8; ++n)
#pragma unroll
        for (int j = 0; j < 4; ++j) acc[n][j] = 0.0f;

    float4 pa[MAXG];
    uint4  pb[2];

    auto ldg_a = [&](int s) {
        const size_t ko = (size_t)s * 64;
#pragma unroll
        for (int i = 0; i < MAXG; ++i)
            if (16 * i < nrows)
                pa[i] = *reinterpret_cast<const float4*>(
                    a_ld + (size_t)(16 * i) * NN + ko);
    };
    auto ldg_b = [&](int s) {
        const size_t ko = (size_t)s * 64;
#pragma unroll
        for (int i = 0; i < 2; ++i)
            pb[i] = *reinterpret_cast<const uint4*>(
                b_ld + (size_t)(32 * i) * NN + ko);
    };
    auto sts_a = [&](uint32_t abase) {
#pragma unroll
        for (int i = 0; i < MAXG; ++i)
            if (16 * i < nrows) {
                __half2 h0 = __floats2half2_rn(pa[i].x, pa[i].y);
                __half2 h1 = __floats2half2_rn(pa[i].z, pa[i].w);
                asm volatile("st.shared.v2.b32 [%0], {%1, %2};"
                             :: "r"(abase + a_sts + (uint32_t)i * 2048),
                                "r"(*(uint32_t*)&h0), "r"(*(uint32_t*)&h1)
                             : "memory");
            }
    };
    auto sts_b = [&](uint32_t bbase) {
#pragma unroll
        for (int i = 0; i < 2; ++i)
            asm volatile("st.shared.v4.b32 [%0], {%1,%2,%3,%4};"
                         :: "r"(bbase + b_sts + (uint32_t)i * 4096),
                            "r"(pb[i].x), "r"(pb[i].y), "r"(pb[i].z), "r"(pb[i].w)
                         : "memory");
    };
    auto compute_sub = [&](uint32_t abase, uint32_t bbase) {
#pragma unroll
        for (int ks = 0; ks < 4; ++ks) {
            uint32_t a0, a1, a2, a3;
            asm volatile(
                "ldmatrix.sync.aligned.m8n8.x4.shared.b16 {%0,%1,%2,%3}, [%4];"
                : "=r"(a0), "=r"(a1), "=r"(a2), "=r"(a3)
                : "r"(abase + SW(a_off + (uint32_t)ks * 32)));
#pragma unroll
            for (int p = 0; p < 4; ++p) {
                uint32_t b0, b1, b2, b3;
                asm volatile(
                    "ldmatrix.sync.aligned.m8n8.x4.shared.b16 {%0,%1,%2,%3}, [%4];"
                    : "=r"(b0), "=r"(b1), "=r"(b2), "=r"(b3)
                    : "r"(bbase + SW(b_off + (uint32_t)p * 2048 + (uint32_t)ks * 32)));
                asm volatile(
                    "mma.sync.aligned.m16n8k16.row.col.f32.f16.f16.f32 "
                    "{%0,%1,%2,%3}, {%4,%5,%6,%7}, {%8,%9}, {%0,%1,%2,%3};"
                    : "+f"(acc[2*p][0]), "+f"(acc[2*p][1]),
                      "+f"(acc[2*p][2]), "+f"(acc[2*p][3])
                    : "r"(a0), "r"(a1), "r"(a2), "r"(a3), "r"(b0), "r"(b1));
                asm volatile(
                    "mma.sync.aligned.m16n8k16.row.col.f32.f16.f16.f32 "
                    "{%0,%1,%2,%3}, {%4,%5,%6,%7}, {%8,%9}, {%0,%1,%2,%3};"
                    : "+f"(acc[2*p+1][0]), "+f"(acc[2*p+1][1]),
                      "+f"(acc[2*p+1][2]), "+f"(acc[2*p+1][3])
                    : "r"(a0), "r"(a1), "r"(a2), "r"(a3), "r"(b2), "r"(b3));
            }
        }
    };

    // ---- pre-barrier A staging (A never needs g_Xt) ----
    ldg_a(0);
    sts_a(sb);      // A sub0 -> buffer0 (convert scratch reuse is CTA-local)
    ldg_a(1);       // A sub1 in flight during the spin

    // ---- wait at global barrier (acquire) ----
    if (tid == 0) {
        unsigned v;
        do {
            asm volatile("ld.acquire.gpu.global.u32 %0, [%1];"
                         : "=r"(v) : "l"(&g_bar));
            if (v >= bar_target) break;
            __nanosleep(32);
        } while (true);
    }
    __syncthreads();

    // ---- post-barrier: B-only prologue ----
    ldg_b(0);
    sts_b(sb + OFF_B);
    sts_a(sb + SUB_A);       // A sub1 from regs
    ldg_b(1);
    sts_b(sb + OFF_B + SUB_B);
    ldg_a(2); ldg_b(2);
    __syncthreads();

    for (int C = 0; C < NIT; ++C) {
        const uint32_t cur = sb + (uint32_t)(C & 1) * STB2;
        const uint32_t nxt = sb + (uint32_t)((C + 1) & 1) * STB2;

        if (2 * C + 2 < NSUB) { sts_a(nxt); sts_b(nxt + OFF_B); }
        if (2 * C + 3 < NSUB) { ldg_a(2 * C + 3); ldg_b(2 * C + 3); }

        if (wid < NG) compute_sub(cur, cur + OFF_B);                 // sub 2C

        if (2 * C + 3 < NSUB) { sts_a(nxt + SUB_A); sts_b(nxt + OFF_B + SUB_B); }
        if (2 * C + 4 < NSUB) { ldg_a(2 * C + 4); ldg_b(2 * C + 4); }

        if (wid < NG) compute_sub(cur + SUB_A, cur + OFF_B + SUB_B); // sub 2C+1

        __syncthreads();
    }

    // ---- epilogue: add bias, store ----
    if (wid < NG) {
        const int g = lane >> 2, q = lane & 3;
        const int mlo = (g0 + wid) * 16 + g;
        float* o0 = out + ((size_t)b * NN + mlo) * FF;
        float* o1 = o0 + (size_t)8 * FF;
#pragma unroll
        for (int nt = 0; nt < 8; ++nt) {
            const int col = nt * 8 + q * 2;
            const float2 bv = *reinterpret_cast<const float2*>(bias + col);
            float2 v0 = make_float2(acc[nt][0] + bv.x, acc[nt][1] + bv.y);
            float2 v1 = make_float2(acc[nt][2] + bv.x, acc[nt][3] + bv.y);
            *reinterpret_cast<float2*>(o0 + col) = v0;
            *reinterpret_cast<float2*>(o1 + col) = v1;
        }
    }
}

extern "C" void kernel_launch(void* const* d_in, const int* in_sizes, int n_in,
                              void* d_out, int out_size)
{
    const float* A    = (const float*)d_in[0]; // adjacent [8,4096,4096]
    const float* X    = (const float*)d_in[1]; // annotations [8,4096,64]
    const float* bias = (const float*)d_in[2]; // bias [1,1,64]
    float* out = (float*)d_out;

    cudaFuncSetAttribute(gemm_f16_final,
                         cudaFuncAttributeMaxDynamicSharedMemorySize, SMEM_DYN);

    gemm_f16_final<<<GRID, 256, SMEM_DYN>>>(A, X, bias, out);
}